// round 1
// baseline (speedup 1.0000x reference)
#include <cuda_runtime.h>
#include <math.h>

// Problem constants
#define BB     8
#define CC     96
#define NN     3136      // 56*56
#define COUT   192
#define TM     64        // query tile rows
#define TK     64        // key tile rows
#define NTILE  49        // NN / TK
#define QS     68        // smem row stride (floats), 16B-aligned, odd-ish banks
#define WTS    196       // W chunk smem stride

#define SMEM_FLOATS (2*CC*QS + TK*QS)       // Qt + Kt (union yT) + Pt (union Wt)
#define SMEM_BYTES  (SMEM_FLOATS * 4)       // 69632

// Scratch (no allocation allowed in kernel_launch)
__device__ float g_y[BB * COUT * NN];       // pre-BN conv output
__device__ float g_scale[COUT];             // gamma * rstd
__device__ float g_shift[COUT];             // beta - mean * gamma * rstd

// ---------------------------------------------------------------------------
// Kernel 1: fused flash self-attention (q=k=v = tokens of x) + max-relative
//           relu(x - att) + concat + 1x1 conv (+bias) -> g_y
// Grid: (49 tiles, 8 batches), 256 threads. Thread (ty,tx) = (tid>>4, tid&15).
// ---------------------------------------------------------------------------
__global__ __launch_bounds__(256)
void attn_conv_kernel(const float* __restrict__ x,
                      const float* __restrict__ w,
                      const float* __restrict__ bias)
{
    extern __shared__ float sm[];
    float* Qt = sm;               // [CC][QS]  Qt[c][i] = x[b][c][n0+i]
    float* Kt = sm + CC * QS;     // [CC][QS]  Kt[c][j] = x[b][c][k0+j]; later xjT
    float* Pt = sm + 2 * CC * QS; // [TK][QS]  Pt[j][i] = softmax numerators
    float* Wt = Pt;               // [16][WTS] conv weight chunk (reuse)
    float* yT = sm;               // [COUT][QS] staged conv output (reuse Qt+Kt)

    const int tid = threadIdx.x;
    const int ty  = tid >> 4;     // 0..15
    const int tx  = tid & 15;     // 0..15
    const int b   = blockIdx.y;
    const int n0  = blockIdx.x * TM;
    const float* xb = x + (size_t)b * CC * NN;

    // Load Q tile (transposed, coalesced over i)
    for (int idx = tid; idx < CC * TM; idx += 256) {
        int c = idx >> 6, i = idx & 63;
        Qt[c * QS + i] = xb[c * NN + n0 + i];
    }

    float m[4], l[4], accO[4][6];
#pragma unroll
    for (int ii = 0; ii < 4; ii++) {
        m[ii] = -1e30f; l[ii] = 0.f;
#pragma unroll
        for (int k = 0; k < 6; k++) accO[ii][k] = 0.f;
    }

    for (int t = 0; t < NTILE; t++) {
        __syncthreads();  // prior PV (reads Kt, Pt) done before overwrite
        const int k0 = t * TK;
        for (int idx = tid; idx < CC * TK; idx += 256) {
            int c = idx >> 6, j = idx & 63;
            Kt[c * QS + j] = xb[c * NN + k0 + j];
        }
        __syncthreads();

        // S = Q * K^T  (4x4 microtile per thread)
        float s[4][4];
#pragma unroll
        for (int ii = 0; ii < 4; ii++)
#pragma unroll
            for (int jj = 0; jj < 4; jj++) s[ii][jj] = 0.f;

        {
            const float* qp = Qt + ty * 4;
            const float* kp = Kt + tx * 4;
#pragma unroll 4
            for (int c = 0; c < CC; c++) {
                float4 qa = *(const float4*)(qp + c * QS);
                float4 kb = *(const float4*)(kp + c * QS);
                s[0][0] = fmaf(qa.x, kb.x, s[0][0]);
                s[0][1] = fmaf(qa.x, kb.y, s[0][1]);
                s[0][2] = fmaf(qa.x, kb.z, s[0][2]);
                s[0][3] = fmaf(qa.x, kb.w, s[0][3]);
                s[1][0] = fmaf(qa.y, kb.x, s[1][0]);
                s[1][1] = fmaf(qa.y, kb.y, s[1][1]);
                s[1][2] = fmaf(qa.y, kb.z, s[1][2]);
                s[1][3] = fmaf(qa.y, kb.w, s[1][3]);
                s[2][0] = fmaf(qa.z, kb.x, s[2][0]);
                s[2][1] = fmaf(qa.z, kb.y, s[2][1]);
                s[2][2] = fmaf(qa.z, kb.z, s[2][2]);
                s[2][3] = fmaf(qa.z, kb.w, s[2][3]);
                s[3][0] = fmaf(qa.w, kb.x, s[3][0]);
                s[3][1] = fmaf(qa.w, kb.y, s[3][1]);
                s[3][2] = fmaf(qa.w, kb.z, s[3][2]);
                s[3][3] = fmaf(qa.w, kb.w, s[3][3]);
            }
        }

        // Online softmax per row (row group = 16 lanes sharing ty)
#pragma unroll
        for (int ii = 0; ii < 4; ii++) {
            float v = fmaxf(fmaxf(s[ii][0], s[ii][1]), fmaxf(s[ii][2], s[ii][3]));
            v = fmaxf(v, __shfl_xor_sync(0xffffffffu, v, 1));
            v = fmaxf(v, __shfl_xor_sync(0xffffffffu, v, 2));
            v = fmaxf(v, __shfl_xor_sync(0xffffffffu, v, 4));
            v = fmaxf(v, __shfl_xor_sync(0xffffffffu, v, 8));
            float mn    = fmaxf(m[ii], v);
            float scale = __expf(m[ii] - mn);
            float ps = 0.f;
#pragma unroll
            for (int jj = 0; jj < 4; jj++) {
                float p = __expf(s[ii][jj] - mn);
                Pt[(tx * 4 + jj) * QS + ty * 4 + ii] = p;
                ps += p;
            }
            ps += __shfl_xor_sync(0xffffffffu, ps, 1);
            ps += __shfl_xor_sync(0xffffffffu, ps, 2);
            ps += __shfl_xor_sync(0xffffffffu, ps, 4);
            ps += __shfl_xor_sync(0xffffffffu, ps, 8);
            l[ii] = l[ii] * scale + ps;
            m[ii] = mn;
#pragma unroll
            for (int k = 0; k < 6; k++) accO[ii][k] *= scale;
        }
        __syncthreads();

        // O += P * V   (V[j][c] == Kt[c][j]); O cols per thread: c = tx + 16k
#pragma unroll 2
        for (int j = 0; j < TK; j++) {
            float4 p4 = *(const float4*)(Pt + j * QS + ty * 4);
#pragma unroll
            for (int k = 0; k < 6; k++) {
                float vj = Kt[(tx + 16 * k) * QS + j];
                accO[0][k] = fmaf(p4.x, vj, accO[0][k]);
                accO[1][k] = fmaf(p4.y, vj, accO[1][k]);
                accO[2][k] = fmaf(p4.z, vj, accO[2][k]);
                accO[3][k] = fmaf(p4.w, vj, accO[3][k]);
            }
        }
    }

    // Finalize attention, compute xj = relu(x - att) into Kt (as xjT[c][i])
    float inv[4];
#pragma unroll
    for (int ii = 0; ii < 4; ii++) inv[ii] = 1.f / l[ii];

    __syncthreads();  // all PV reads of Kt done
#pragma unroll
    for (int ii = 0; ii < 4; ii++) {
#pragma unroll
        for (int k = 0; k < 6; k++) {
            int c = tx + 16 * k;
            float att = accO[ii][k] * inv[ii];
            float xv  = Qt[c * QS + ty * 4 + ii];
            Kt[c * QS + ty * 4 + ii] = fmaxf(xv - att, 0.f);
        }
    }
    __syncthreads();

    // 1x1 conv: y[i][o] = sum_cc W[o][cc] * cat[cc][i],  cat = [Qt ; xjT]
    // Thread owns rows i = ty*4.., cols o = tx + 16*kk (kk=0..11)
    float accY[4][12];
#pragma unroll
    for (int ii = 0; ii < 4; ii++)
#pragma unroll
        for (int kk = 0; kk < 12; kk++) accY[ii][kk] = 0.f;

    for (int ch = 0; ch < 12; ch++) {          // 12 chunks x 16 input channels
        __syncthreads();
        for (int idx = tid; idx < 16 * COUT; idx += 256) {
            int o = idx >> 4, r = idx & 15;
            Wt[r * WTS + o] = w[o * (2 * CC) + ch * 16 + r];
        }
        __syncthreads();
        const float* src = (ch < 6) ? (Qt + (ch * 16) * QS)
                                    : (Kt + ((ch - 6) * 16) * QS);
#pragma unroll
        for (int r = 0; r < 16; r++) {
            float4 xa = *(const float4*)(src + r * QS + ty * 4);
#pragma unroll
            for (int kk = 0; kk < 12; kk++) {
                float wv = Wt[r * WTS + tx + 16 * kk];
                accY[0][kk] = fmaf(xa.x, wv, accY[0][kk]);
                accY[1][kk] = fmaf(xa.y, wv, accY[1][kk]);
                accY[2][kk] = fmaf(xa.z, wv, accY[2][kk]);
                accY[3][kk] = fmaf(xa.w, wv, accY[3][kk]);
            }
        }
    }

    __syncthreads();  // done reading Qt/Kt; reuse region as yT
#pragma unroll
    for (int ii = 0; ii < 4; ii++) {
#pragma unroll
        for (int kk = 0; kk < 12; kk++) {
            int o = tx + 16 * kk;
            yT[o * QS + ty * 4 + ii] = accY[ii][kk] + bias[o];
        }
    }
    __syncthreads();

    float* yb = g_y + ((size_t)b * COUT) * NN + n0;
    for (int idx = tid; idx < COUT * TM; idx += 256) {
        int o = idx >> 6, i = idx & 63;
        yb[o * NN + i] = yT[o * QS + i];
    }
}

// ---------------------------------------------------------------------------
// Kernel 2: per-channel BN stats (biased var over B*H*W), no atomics.
// ---------------------------------------------------------------------------
__global__ __launch_bounds__(256)
void bn_stats_kernel(const float* __restrict__ gamma,
                     const float* __restrict__ beta)
{
    const int ch = blockIdx.x;
    float s = 0.f, ss = 0.f;
    for (int b = 0; b < BB; b++) {
        const float* p = g_y + ((size_t)b * COUT + ch) * NN;
        for (int i = threadIdx.x; i < NN; i += 256) {
            float v = p[i];
            s += v; ss += v * v;
        }
    }
    __shared__ float rs[256], rss[256];
    rs[threadIdx.x] = s; rss[threadIdx.x] = ss;
    __syncthreads();
    for (int o = 128; o > 0; o >>= 1) {
        if (threadIdx.x < o) {
            rs[threadIdx.x]  += rs[threadIdx.x + o];
            rss[threadIdx.x] += rss[threadIdx.x + o];
        }
        __syncthreads();
    }
    if (threadIdx.x == 0) {
        const float cnt  = (float)(BB * NN);
        float mean = rs[0] / cnt;
        float var  = rss[0] / cnt - mean * mean;
        float rstd = rsqrtf(var + 1e-5f);
        float a    = gamma[ch] * rstd;
        g_scale[ch] = a;
        g_shift[ch] = beta[ch] - mean * a;
    }
}

// ---------------------------------------------------------------------------
// Kernel 3: normalize + exact GELU (erf via normcdf), vectorized float4.
// ---------------------------------------------------------------------------
__global__ __launch_bounds__(256)
void bn_gelu_kernel(float* __restrict__ out)
{
    const int i4 = blockIdx.x * blockDim.x + threadIdx.x;
    const int total4 = BB * COUT * NN / 4;
    if (i4 >= total4) return;
    const int ch = (i4 / (NN / 4)) % COUT;
    const float a  = g_scale[ch];
    const float sh = g_shift[ch];
    float4 v = ((const float4*)g_y)[i4];
    v.x = v.x * a + sh;  v.x = v.x * normcdff(v.x);
    v.y = v.y * a + sh;  v.y = v.y * normcdff(v.y);
    v.z = v.z * a + sh;  v.z = v.z * normcdff(v.z);
    v.w = v.w * a + sh;  v.w = v.w * normcdff(v.w);
    ((float4*)out)[i4] = v;
}

// ---------------------------------------------------------------------------
extern "C" void kernel_launch(void* const* d_in, const int* in_sizes, int n_in,
                              void* d_out, int out_size)
{
    const float* x     = (const float*)d_in[0];
    const float* w     = (const float*)d_in[1];
    const float* cbias = (const float*)d_in[2];
    const float* gamma = (const float*)d_in[3];
    const float* beta  = (const float*)d_in[4];
    float* out = (float*)d_out;

    cudaFuncSetAttribute(attn_conv_kernel,
                         cudaFuncAttributeMaxDynamicSharedMemorySize, SMEM_BYTES);

    attn_conv_kernel<<<dim3(NTILE, BB), 256, SMEM_BYTES>>>(x, w, cbias);
    bn_stats_kernel<<<COUT, 256>>>(gamma, beta);
    bn_gelu_kernel<<<(BB * COUT * NN / 4 + 255) / 256, 256>>>(out);
}